// round 1
// baseline (speedup 1.0000x reference)
#include <cuda_runtime.h>
#include <cstdint>

#define B_ 4
#define S_ 2048
#define H_ 16
#define D_ 64
#define HID 1024
#define BH_ (B_ * H_)

// Scratch (allocation-free rule: __device__ globals)
__device__ float g_q[(size_t)BH_ * S_ * D_];    // [B,H,S,D]
__device__ float g_k[(size_t)BH_ * S_ * D_];
__device__ float g_v[(size_t)BH_ * S_ * D_];
__device__ float g_ctx[(size_t)B_ * S_ * HID];  // [B,S,HID]

// ---------------------------------------------------------------------------
// Fused QKV projection: C[m, n] = sum_k X[m,k] * W[n,k] + b[n]
// M = 8192, N = 3072 (Wq | Wk | Wv), K = 1024.
// 128x128 block tile, BK=16, 8x8 per-thread micro-tile, 256 threads.
// Epilogue scatters into [B,H,S,D] layout.
// ---------------------------------------------------------------------------
__global__ __launch_bounds__(256) void qkv_gemm(
    const float* __restrict__ X,
    const float* __restrict__ Wq, const float* __restrict__ bq,
    const float* __restrict__ Wk, const float* __restrict__ bk,
    const float* __restrict__ Wv, const float* __restrict__ bv)
{
    constexpr int BM = 128, BN = 128, BK = 16;
    __shared__ float As[BK][BM + 4];
    __shared__ float Bs[BK][BN + 4];

    const int tid = threadIdx.x;
    const int m0 = blockIdx.y * BM;
    const int n0 = blockIdx.x * BN;

    const int which = n0 >> 10;          // 0=Q 1=K 2=V (1024 % 128 == 0, no straddle)
    const int nl0 = n0 & 1023;
    const float* W    = (which == 0) ? Wq : (which == 1) ? Wk : Wv;
    const float* bias = (which == 0) ? bq : (which == 1) ? bk : bv;
    float* dst        = (which == 0) ? g_q : (which == 1) ? g_k : g_v;

    const int tr = tid >> 4;   // 0..15
    const int tc = tid & 15;   // 0..15

    float acc[8][8];
#pragma unroll
    for (int i = 0; i < 8; ++i)
#pragma unroll
        for (int j = 0; j < 8; ++j) acc[i][j] = 0.f;

    for (int k0 = 0; k0 < HID; k0 += BK) {
#pragma unroll
        for (int it = 0; it < 2; ++it) {
            int idx = tid + it * 256;
            int row = idx >> 2;
            int kq  = (idx & 3) * 4;
            float4 xv = *(const float4*)(X + (size_t)(m0 + row) * HID + k0 + kq);
            As[kq + 0][row] = xv.x; As[kq + 1][row] = xv.y;
            As[kq + 2][row] = xv.z; As[kq + 3][row] = xv.w;
            float4 wv = *(const float4*)(W + (size_t)(nl0 + row) * HID + k0 + kq);
            Bs[kq + 0][row] = wv.x; Bs[kq + 1][row] = wv.y;
            Bs[kq + 2][row] = wv.z; Bs[kq + 3][row] = wv.w;
        }
        __syncthreads();
#pragma unroll
        for (int k = 0; k < BK; ++k) {
            float a[8], b[8];
            *(float4*)&a[0] = *(float4*)&As[k][tr * 8];
            *(float4*)&a[4] = *(float4*)&As[k][tr * 8 + 4];
            *(float4*)&b[0] = *(float4*)&Bs[k][tc * 8];
            *(float4*)&b[4] = *(float4*)&Bs[k][tc * 8 + 4];
#pragma unroll
            for (int i = 0; i < 8; ++i)
#pragma unroll
                for (int j = 0; j < 8; ++j) acc[i][j] += a[i] * b[j];
        }
        __syncthreads();
    }

    // Epilogue: add bias, scatter into [B,H,S,D]
    float bv8[8];
#pragma unroll
    for (int j = 0; j < 8; ++j) bv8[j] = bias[nl0 + tc * 8 + j];

    const int nl_base = nl0 + tc * 8;      // 8-aligned
    const int h  = nl_base >> 6;           // constant over j (8 | 64)
    const int d0 = nl_base & 63;

#pragma unroll
    for (int i = 0; i < 8; ++i) {
        int m = m0 + tr * 8 + i;
        int b_idx = m >> 11;
        int s = m & 2047;
        float* p = dst + (((size_t)(b_idx * H_ + h) * S_ + s) * D_ + d0);
        float4 o0 = make_float4(acc[i][0] + bv8[0], acc[i][1] + bv8[1],
                                acc[i][2] + bv8[2], acc[i][3] + bv8[3]);
        float4 o1 = make_float4(acc[i][4] + bv8[4], acc[i][5] + bv8[5],
                                acc[i][6] + bv8[6], acc[i][7] + bv8[7]);
        *(float4*)(p)     = o0;
        *(float4*)(p + 4) = o1;
    }
}

// ---------------------------------------------------------------------------
// Flash attention: one block per (bh, 64-query tile). 64-key tiles,
// online softmax, fp32. Writes context in [B,S,HID] layout.
// ---------------------------------------------------------------------------
__global__ __launch_bounds__(256) void attn_kernel(const float* __restrict__ head_mask)
{
    extern __shared__ float sm[];
    float* Qt  = sm;                 // [64][64] Qt[d][r]  (transposed, pre-scaled)
    float* Kt  = Qt + 64 * 64;       // [64][64] Kt[d][c]
    float* Vs  = Kt + 64 * 64;       // [64][64] Vs[j][d]
    float* Ss  = Vs + 64 * 64;       // [64][65] scores / probs
    float* m_s = Ss + 64 * 65;       // [64]
    float* l_s = m_s + 64;           // [64]
    float* f_s = l_s + 64;           // [64]

    const int tid = threadIdx.x;
    const int bh  = blockIdx.y;
    const int s0  = blockIdx.x * 64;

    const float* Q = g_q + (size_t)bh * S_ * D_;
    const float* K = g_k + (size_t)bh * S_ * D_;
    const float* V = g_v + (size_t)bh * S_ * D_;

    const float scale = 0.125f;  // 1/sqrt(64)

    // Load Q tile (transposed + pre-scaled)
#pragma unroll
    for (int it = 0; it < 4; ++it) {
        int lin = tid + it * 256;        // 0..1023
        int row = lin >> 4;
        int dq  = (lin & 15) * 4;
        float4 qv = *(const float4*)(Q + (size_t)(s0 + row) * D_ + dq);
        Qt[(dq + 0) * 64 + row] = qv.x * scale;
        Qt[(dq + 1) * 64 + row] = qv.y * scale;
        Qt[(dq + 2) * 64 + row] = qv.z * scale;
        Qt[(dq + 3) * 64 + row] = qv.w * scale;
    }
    if (tid < 64) { m_s[tid] = -__int_as_float(0x7f800000); l_s[tid] = 0.f; }

    const int tr = tid >> 4, tc = tid & 15;
    const int r0 = tr * 4, c0 = tc * 4;

    float acc[4][4];
#pragma unroll
    for (int i = 0; i < 4; ++i)
#pragma unroll
        for (int j = 0; j < 4; ++j) acc[i][j] = 0.f;

    for (int kt = 0; kt < S_ / 64; ++kt) {
        __syncthreads();  // previous iteration's PV done before overwriting tiles
        // Load K (transposed) and V (natural) tiles
#pragma unroll
        for (int it = 0; it < 4; ++it) {
            int lin = tid + it * 256;
            int row = lin >> 4;
            int dq  = (lin & 15) * 4;
            float4 kv = *(const float4*)(K + (size_t)(kt * 64 + row) * D_ + dq);
            Kt[(dq + 0) * 64 + row] = kv.x;
            Kt[(dq + 1) * 64 + row] = kv.y;
            Kt[(dq + 2) * 64 + row] = kv.z;
            Kt[(dq + 3) * 64 + row] = kv.w;
            float4 vv = *(const float4*)(V + (size_t)(kt * 64 + row) * D_ + dq);
            *(float4*)&Vs[row * 64 + dq] = vv;
        }
        __syncthreads();

        // S = (Q * scale) @ K^T  -> Ss
        float sacc[4][4];
#pragma unroll
        for (int i = 0; i < 4; ++i)
#pragma unroll
            for (int j = 0; j < 4; ++j) sacc[i][j] = 0.f;

#pragma unroll 8
        for (int d = 0; d < 64; ++d) {
            float4 a = *(float4*)&Qt[d * 64 + r0];
            float4 b = *(float4*)&Kt[d * 64 + c0];
            float av[4] = {a.x, a.y, a.z, a.w};
            float bvv[4] = {b.x, b.y, b.z, b.w};
#pragma unroll
            for (int i = 0; i < 4; ++i)
#pragma unroll
                for (int j = 0; j < 4; ++j) sacc[i][j] += av[i] * bvv[j];
        }
#pragma unroll
        for (int i = 0; i < 4; ++i)
#pragma unroll
            for (int j = 0; j < 4; ++j) Ss[(r0 + i) * 65 + c0 + j] = sacc[i][j];
        __syncthreads();

        // Online softmax: 4 threads per row
        {
            int row  = tid >> 2;
            int part = tid & 3;
            float* srow = Ss + row * 65 + part * 16;
            float mx = srow[0];
#pragma unroll
            for (int u = 1; u < 16; ++u) mx = fmaxf(mx, srow[u]);
            mx = fmaxf(mx, __shfl_xor_sync(0xffffffffu, mx, 1));
            mx = fmaxf(mx, __shfl_xor_sync(0xffffffffu, mx, 2));
            float m_old = m_s[row];
            float m_new = fmaxf(m_old, mx);
            float ps = 0.f;
#pragma unroll
            for (int u = 0; u < 16; ++u) {
                float p = __expf(srow[u] - m_new);
                srow[u] = p;
                ps += p;
            }
            ps += __shfl_xor_sync(0xffffffffu, ps, 1);
            ps += __shfl_xor_sync(0xffffffffu, ps, 2);
            if (part == 0) {
                float f = __expf(m_old - m_new);
                f_s[row] = f;
                l_s[row] = l_s[row] * f + ps;
                m_s[row] = m_new;
            }
        }
        __syncthreads();

        // Rescale accumulator + accumulate P @ V
#pragma unroll
        for (int i = 0; i < 4; ++i) {
            float f = f_s[r0 + i];
#pragma unroll
            for (int j = 0; j < 4; ++j) acc[i][j] *= f;
        }
#pragma unroll 4
        for (int j2 = 0; j2 < 64; ++j2) {
            float4 vv = *(float4*)&Vs[j2 * 64 + c0];
            float p0 = Ss[(r0 + 0) * 65 + j2];
            float p1 = Ss[(r0 + 1) * 65 + j2];
            float p2 = Ss[(r0 + 2) * 65 + j2];
            float p3 = Ss[(r0 + 3) * 65 + j2];
            acc[0][0] += p0 * vv.x; acc[0][1] += p0 * vv.y; acc[0][2] += p0 * vv.z; acc[0][3] += p0 * vv.w;
            acc[1][0] += p1 * vv.x; acc[1][1] += p1 * vv.y; acc[1][2] += p1 * vv.z; acc[1][3] += p1 * vv.w;
            acc[2][0] += p2 * vv.x; acc[2][1] += p2 * vv.y; acc[2][2] += p2 * vv.z; acc[2][3] += p2 * vv.w;
            acc[3][0] += p3 * vv.x; acc[3][1] += p3 * vv.y; acc[3][2] += p3 * vv.z; acc[3][3] += p3 * vv.w;
        }
    }

    // Normalize, apply head mask, write context [B,S,HID]
    const int b_idx = bh >> 4;
    const int h     = bh & 15;
    const float mask = head_mask[h];
#pragma unroll
    for (int i = 0; i < 4; ++i) {
        float inv = mask / l_s[r0 + i];
        int s = s0 + r0 + i;
        float4 o = make_float4(acc[i][0] * inv, acc[i][1] * inv,
                               acc[i][2] * inv, acc[i][3] * inv);
        *(float4*)&g_ctx[((size_t)b_idx * S_ + s) * HID + h * 64 + c0] = o;
    }
}

// ---------------------------------------------------------------------------
// Output projection: out = ctx @ Wo^T + bo.  M=8192, N=1024, K=1024.
// ---------------------------------------------------------------------------
__global__ __launch_bounds__(256) void oproj_gemm(
    const float* __restrict__ Wo, const float* __restrict__ bo,
    float* __restrict__ out)
{
    constexpr int BM = 128, BN = 128, BK = 16;
    __shared__ float As[BK][BM + 4];
    __shared__ float Bs[BK][BN + 4];

    const int tid = threadIdx.x;
    const int m0 = blockIdx.y * BM;
    const int n0 = blockIdx.x * BN;
    const float* X = g_ctx;

    const int tr = tid >> 4;
    const int tc = tid & 15;

    float acc[8][8];
#pragma unroll
    for (int i = 0; i < 8; ++i)
#pragma unroll
        for (int j = 0; j < 8; ++j) acc[i][j] = 0.f;

    for (int k0 = 0; k0 < HID; k0 += BK) {
#pragma unroll
        for (int it = 0; it < 2; ++it) {
            int idx = tid + it * 256;
            int row = idx >> 2;
            int kq  = (idx & 3) * 4;
            float4 xv = *(const float4*)(X + (size_t)(m0 + row) * HID + k0 + kq);
            As[kq + 0][row] = xv.x; As[kq + 1][row] = xv.y;
            As[kq + 2][row] = xv.z; As[kq + 3][row] = xv.w;
            float4 wv = *(const float4*)(Wo + (size_t)(n0 + row) * HID + k0 + kq);
            Bs[kq + 0][row] = wv.x; Bs[kq + 1][row] = wv.y;
            Bs[kq + 2][row] = wv.z; Bs[kq + 3][row] = wv.w;
        }
        __syncthreads();
#pragma unroll
        for (int k = 0; k < BK; ++k) {
            float a[8], b[8];
            *(float4*)&a[0] = *(float4*)&As[k][tr * 8];
            *(float4*)&a[4] = *(float4*)&As[k][tr * 8 + 4];
            *(float4*)&b[0] = *(float4*)&Bs[k][tc * 8];
            *(float4*)&b[4] = *(float4*)&Bs[k][tc * 8 + 4];
#pragma unroll
            for (int i = 0; i < 8; ++i)
#pragma unroll
                for (int j = 0; j < 8; ++j) acc[i][j] += a[i] * b[j];
        }
        __syncthreads();
    }

    float bv8[8];
#pragma unroll
    for (int j = 0; j < 8; ++j) bv8[j] = bo[n0 + tc * 8 + j];

#pragma unroll
    for (int i = 0; i < 8; ++i) {
        int m = m0 + tr * 8 + i;
        float* p = out + (size_t)m * HID + n0 + tc * 8;
        float4 o0 = make_float4(acc[i][0] + bv8[0], acc[i][1] + bv8[1],
                                acc[i][2] + bv8[2], acc[i][3] + bv8[3]);
        float4 o1 = make_float4(acc[i][4] + bv8[4], acc[i][5] + bv8[5],
                                acc[i][6] + bv8[6], acc[i][7] + bv8[7]);
        *(float4*)(p)     = o0;
        *(float4*)(p + 4) = o1;
    }
}

// ---------------------------------------------------------------------------
extern "C" void kernel_launch(void* const* d_in, const int* in_sizes, int n_in,
                              void* d_out, int out_size)
{
    const float* x  = (const float*)d_in[0];
    const float* Wq = (const float*)d_in[1];
    const float* bq = (const float*)d_in[2];
    const float* Wk = (const float*)d_in[3];
    const float* bk = (const float*)d_in[4];
    const float* Wv = (const float*)d_in[5];
    const float* bv = (const float*)d_in[6];
    const float* Wo = (const float*)d_in[7];
    const float* bo = (const float*)d_in[8];
    const float* head_mask = (const float*)d_in[9];
    float* out = (float*)d_out;

    // QKV projection: N = 3072 -> 24 tiles, M = 8192 -> 64 tiles
    qkv_gemm<<<dim3(24, 64), 256>>>(x, Wq, bq, Wk, bk, Wv, bv);

    // Attention: 32 query tiles x 64 (b,h) pairs
    const int attn_smem = (64 * 64 * 3 + 64 * 65 + 3 * 64) * (int)sizeof(float);
    static bool attr_set = false;
    if (!attr_set) {
        cudaFuncSetAttribute(attn_kernel, cudaFuncAttributeMaxDynamicSharedMemorySize, attn_smem);
        attr_set = true;
    }
    attn_kernel<<<dim3(32, 64), 256, attn_smem>>>(head_mask);

    // O projection
    oproj_gemm<<<dim3(8, 64), 256>>>(Wo, bo, out);
}

// round 3
// speedup vs baseline: 3.1111x; 3.1111x over previous
#include <cuda_runtime.h>
#include <cstdint>

#define B_ 4
#define S_ 2048
#define H_ 16
#define D_ 64
#define HID 1024
#define BH_ (B_ * H_)

// ---------------------------------------------------------------------------
// Device scratch (allocation-free rule)
// ---------------------------------------------------------------------------
__device__ float g_q[(size_t)BH_ * S_ * D_];    // [B,H,S,D] tf32-rounded
__device__ float g_k[(size_t)BH_ * S_ * D_];
__device__ float g_v[(size_t)BH_ * S_ * D_];
__device__ float g_ctx[(size_t)B_ * S_ * HID];  // [B,S,HID] tf32-rounded
__device__ float g_xr[(size_t)B_ * S_ * HID];   // x rounded to tf32
__device__ float g_wr[4 * (size_t)HID * HID];   // Wq|Wk|Wv|Wo rounded to tf32

// ---------------------------------------------------------------------------
// Helpers
// ---------------------------------------------------------------------------
__device__ __forceinline__ float rtf32(float x) {
    uint32_t u;
    asm("cvt.rna.tf32.f32 %0, %1;" : "=r"(u) : "f"(x));
    return __uint_as_float(u);
}

__device__ __forceinline__ uint32_t fu(float x) { return __float_as_uint(x); }

// mma.sync m16n8k8 tf32, fp32 accumulate (compute_80+, legal at compute_103)
__device__ __forceinline__ void mma8(float* d, const uint32_t* a, const uint32_t* b) {
    asm volatile(
        "mma.sync.aligned.m16n8k8.row.col.f32.tf32.tf32.f32 "
        "{%0,%1,%2,%3}, {%4,%5,%6,%7}, {%8,%9}, {%0,%1,%2,%3};"
        : "+f"(d[0]), "+f"(d[1]), "+f"(d[2]), "+f"(d[3])
        : "r"(a[0]), "r"(a[1]), "r"(a[2]), "r"(a[3]), "r"(b[0]), "r"(b[1]));
}

__device__ __forceinline__ uint32_t smem_u32(const void* p) {
    uint32_t a;
    asm("{ .reg .u64 t; cvta.to.shared.u64 t, %1; cvt.u32.u64 %0, t; }"
        : "=r"(a) : "l"(p));
    return a;
}
__device__ __forceinline__ void cpa16(uint32_t s, const void* g) {
    asm volatile("cp.async.cg.shared.global [%0], [%1], 16;" :: "r"(s), "l"(g));
}
__device__ __forceinline__ void cpa_commit() {
    asm volatile("cp.async.commit_group;" ::: "memory");
}
template <int N> __device__ __forceinline__ void cpa_wait() {
    asm volatile("cp.async.wait_group %0;" :: "n"(N) : "memory");
}

// ---------------------------------------------------------------------------
// Round inputs to tf32 (RNA; HW path would truncate -> biased)
// which: 0 -> g_xr, 1..4 -> g_wr quadrant (Wq,Wk,Wv,Wo)
// ---------------------------------------------------------------------------
__global__ void round_k(const float4* __restrict__ src, int which, int n4)
{
    int i = blockIdx.x * blockDim.x + threadIdx.x;
    if (i >= n4) return;
    float4* dst = (which == 0) ? (float4*)g_xr
                               : (float4*)(g_wr + (size_t)(which - 1) * HID * HID);
    float4 v = src[i];
    v.x = rtf32(v.x); v.y = rtf32(v.y); v.z = rtf32(v.z); v.w = rtf32(v.w);
    dst[i] = v;
}

// ---------------------------------------------------------------------------
// Projection GEMM on mma.sync tf32.
// C[m,n] = A[m,:] . W[n,:] + bias[n]
// Block tile 128m x 256n, BK=16, 256 threads (8 warps, warp tile 64x64).
// Smem strides: 20 words per 16-k row (stride % 32 == 20 -> bank = (20r+c)%32,
// conflict-free for the m16n8k8 fragment patterns).
// mode 0: QKV (blockIdx.x selects Q/K/V and 256-col slice; scatter to [B,H,S,D],
//         tf32-rounded).  mode 1: O-proj (flat fp32 out).
// ---------------------------------------------------------------------------
#define PJ_AS (128 * 20)
#define PJ_BS (256 * 20)
static constexpr int PROJ_SMEM = (2 * PJ_AS + 2 * PJ_BS) * 4;  // 61440 B

__global__ __launch_bounds__(256, 1) void proj_tc(
    const float* __restrict__ Aall, int mode,
    const float* __restrict__ bq, const float* __restrict__ bk,
    const float* __restrict__ bv, const float* __restrict__ bo,
    float* __restrict__ outflat)
{
    extern __shared__ float sm[];
    float* As = sm;                 // [2][128*20]
    float* Bs = sm + 2 * PJ_AS;     // [2][256*20]

    const int tid = threadIdx.x;
    const int m0  = blockIdx.y * 128;

    int which, n0g;
    const float* bias;
    if (mode == 0) {
        which = blockIdx.x >> 2;             // 0=Q 1=K 2=V
        n0g   = (blockIdx.x & 3) * 256;
        bias  = (which == 0) ? bq : (which == 1) ? bk : bv;
    } else {
        which = 3;
        n0g   = blockIdx.x * 256;
        bias  = bo;
    }
    const float* Wb = g_wr + (size_t)which * HID * HID + (size_t)n0g * HID;
    const float* Ab = Aall + (size_t)m0 * HID;

    const uint32_t sb = smem_u32(sm);

    // loader: BK=16 slab kt into buffer bi
    auto load_slab = [&](int kt, int bi) {
        const uint32_t abase = sb + (uint32_t)(bi * PJ_AS) * 4u;
        const uint32_t bbase = sb + (uint32_t)(2 * PJ_AS + bi * PJ_BS) * 4u;
        const int k0 = kt * 16;
        // A: 512 float4
#pragma unroll
        for (int it = 0; it < 2; ++it) {
            int f = tid + it * 256;
            int row = f >> 2, kq = (f & 3) * 4;
            cpa16(abase + (uint32_t)(row * 20 + kq) * 4u,
                  Ab + (size_t)row * HID + k0 + kq);
        }
        // B: 1024 float4
#pragma unroll
        for (int it = 0; it < 4; ++it) {
            int f = tid + it * 256;
            int row = f >> 2, kq = (f & 3) * 4;
            cpa16(bbase + (uint32_t)(row * 20 + kq) * 4u,
                  Wb + (size_t)row * HID + k0 + kq);
        }
        cpa_commit();
    };

    const int w    = tid >> 5;
    const int lane = tid & 31;
    const int r    = lane >> 2;
    const int c    = lane & 3;
    const int wm   = (w & 1) * 64;    // warp m offset
    const int wn   = (w >> 1) * 64;   // warp n offset

    float acc[4][8][4];
#pragma unroll
    for (int i = 0; i < 4; ++i)
#pragma unroll
        for (int j = 0; j < 8; ++j)
#pragma unroll
            for (int q = 0; q < 4; ++q) acc[i][j][q] = 0.f;

    load_slab(0, 0);

    for (int kt = 0; kt < 64; ++kt) {
        cpa_wait<0>();
        __syncthreads();
        if (kt + 1 < 64) load_slab(kt + 1, (kt + 1) & 1);

        const float* as = As + (kt & 1) * PJ_AS + (wm + r) * 20;
        const float* bs = Bs + (kt & 1) * PJ_BS + (wn + r) * 20;

#pragma unroll
        for (int ks = 0; ks < 16; ks += 8) {
            uint32_t af[4][4];
#pragma unroll
            for (int i = 0; i < 4; ++i) {
                const float* p = as + i * 16 * 20 + ks + c;
                af[i][0] = fu(p[0]);
                af[i][1] = fu(p[8 * 20]);
                af[i][2] = fu(p[4]);
                af[i][3] = fu(p[8 * 20 + 4]);
            }
#pragma unroll
            for (int j = 0; j < 8; ++j) {
                const float* p = bs + j * 8 * 20 + ks + c;
                uint32_t bf[2] = { fu(p[0]), fu(p[4]) };
#pragma unroll
                for (int i = 0; i < 4; ++i) mma8(acc[i][j], af[i], bf);
            }
        }
        __syncthreads();
    }

    // Epilogue
    if (mode == 0) {
        float* dst = (which == 0) ? g_q : (which == 1) ? g_k : g_v;
#pragma unroll
        for (int j = 0; j < 8; ++j) {
            const int nl = n0g + wn + j * 8 + 2 * c;   // within [0,1024)
            const float b0 = bias[nl], b1 = bias[nl + 1];
            const int h  = nl >> 6;
            const int dd = nl & 63;
#pragma unroll
            for (int i = 0; i < 4; ++i) {
                int m = m0 + wm + i * 16 + r;
                int bi = m >> 11, s = m & 2047;
                float* p = dst + (((size_t)(bi * H_ + h) * S_ + s) * D_ + dd);
                float2 v0 = make_float2(rtf32(acc[i][j][0] + b0),
                                        rtf32(acc[i][j][1] + b1));
                *(float2*)p = v0;
                float2 v1 = make_float2(rtf32(acc[i][j][2] + b0),
                                        rtf32(acc[i][j][3] + b1));
                *(float2*)(p + 8 * D_) = v1;   // m+8: same (b,h), s+8
            }
        }
    } else {
#pragma unroll
        for (int j = 0; j < 8; ++j) {
            const int n = n0g + wn + j * 8 + 2 * c;
            const float b0 = bias[n], b1 = bias[n + 1];
#pragma unroll
            for (int i = 0; i < 4; ++i) {
                int m = m0 + wm + i * 16 + r;
                float* p = outflat + (size_t)m * HID + n;
                *(float2*)p = make_float2(acc[i][j][0] + b0, acc[i][j][1] + b1);
                *(float2*)(p + 8 * HID) =
                    make_float2(acc[i][j][2] + b0, acc[i][j][3] + b1);
            }
        }
    }
}

// ---------------------------------------------------------------------------
// Flash attention on mma.sync tf32.
// Block = (128 q-rows, one bh). 256 threads = 8 warps.
// QK: warp tile 32q x 32k (wm=w&3, wn=w>>2); PV: warp tile 32q x 32d.
// Smem strides: Qs/Ks/Ss = 68 (A/K-pattern), Vs = 72 (B-pattern).
// ---------------------------------------------------------------------------
#define AT_QS (128 * 68)
#define AT_KS (64 * 68)
#define AT_VS (64 * 72)
#define AT_SS (128 * 68)
static constexpr int ATTN_SMEM = (AT_QS + AT_KS + AT_VS + AT_SS + 3 * 128) * 4;

__global__ __launch_bounds__(256, 1) void attn_tc(const float* __restrict__ head_mask)
{
    extern __shared__ float sm[];
    float* Qs  = sm;
    float* Ks  = Qs + AT_QS;
    float* Vs  = Ks + AT_KS;
    float* Ss  = Vs + AT_VS;
    float* m_s = Ss + AT_SS;
    float* l_s = m_s + 128;
    float* f_s = l_s + 128;

    const int tid = threadIdx.x;
    const int bh  = blockIdx.y;
    const int s0  = blockIdx.x * 128;

    const float* Q = g_q + (size_t)bh * S_ * D_;
    const float* K = g_k + (size_t)bh * S_ * D_;
    const float* V = g_v + (size_t)bh * S_ * D_;

    // Load Q tile, pre-scaled by 1/8 (power of 2: preserves tf32 rounding)
#pragma unroll
    for (int it = 0; it < 8; ++it) {
        int f = tid + it * 256;
        int row = f >> 4, dq = (f & 15) * 4;
        float4 qv = *(const float4*)(Q + (size_t)(s0 + row) * D_ + dq);
        qv.x *= 0.125f; qv.y *= 0.125f; qv.z *= 0.125f; qv.w *= 0.125f;
        *(float4*)&Qs[row * 68 + dq] = qv;
    }
    if (tid < 128) { m_s[tid] = -__int_as_float(0x7f800000); l_s[tid] = 0.f; }

    const int w    = tid >> 5;
    const int lane = tid & 31;
    const int r    = lane >> 2;
    const int c    = lane & 3;
    const int wm   = (w & 3) * 32;
    const int wn   = (w >> 2) * 32;

    float oacc[2][4][4];
#pragma unroll
    for (int i = 0; i < 2; ++i)
#pragma unroll
        for (int j = 0; j < 4; ++j)
#pragma unroll
            for (int q = 0; q < 4; ++q) oacc[i][j][q] = 0.f;

    for (int kt = 0; kt < S_ / 64; ++kt) {
        __syncthreads();   // prior PV reads of Ks/Vs/Ss complete
        // Load K and V 64-row tiles
#pragma unroll
        for (int it = 0; it < 4; ++it) {
            int f = tid + it * 256;
            int row = f >> 4, dq = (f & 15) * 4;
            float4 kv = *(const float4*)(K + (size_t)(kt * 64 + row) * D_ + dq);
            *(float4*)&Ks[row * 68 + dq] = kv;
            float4 vv = *(const float4*)(V + (size_t)(kt * 64 + row) * D_ + dq);
            *(float4*)&Vs[row * 72 + dq] = vv;
        }
        __syncthreads();

        // --- S = Q @ K^T ---
        float sacc[2][4][4];
#pragma unroll
        for (int i = 0; i < 2; ++i)
#pragma unroll
            for (int j = 0; j < 4; ++j)
#pragma unroll
                for (int q = 0; q < 4; ++q) sacc[i][j][q] = 0.f;

#pragma unroll
        for (int ks = 0; ks < 64; ks += 8) {
            uint32_t af[2][4];
#pragma unroll
            for (int i = 0; i < 2; ++i) {
                const float* p = Qs + (wm + i * 16 + r) * 68 + ks + c;
                af[i][0] = fu(p[0]);
                af[i][1] = fu(p[8 * 68]);
                af[i][2] = fu(p[4]);
                af[i][3] = fu(p[8 * 68 + 4]);
            }
#pragma unroll
            for (int j = 0; j < 4; ++j) {
                const float* p = Ks + (wn + j * 8 + r) * 68 + ks + c;
                uint32_t bf[2] = { fu(p[0]), fu(p[4]) };
#pragma unroll
                for (int i = 0; i < 2; ++i) mma8(sacc[i][j], af[i], bf);
            }
        }
        // Write S to smem
#pragma unroll
        for (int i = 0; i < 2; ++i) {
            int rr = wm + i * 16 + r;
#pragma unroll
            for (int j = 0; j < 4; ++j) {
                int cc = wn + j * 8 + 2 * c;
                *(float2*)&Ss[rr * 68 + cc]       = make_float2(sacc[i][j][0], sacc[i][j][1]);
                *(float2*)&Ss[(rr + 8) * 68 + cc] = make_float2(sacc[i][j][2], sacc[i][j][3]);
            }
        }
        __syncthreads();

        // --- online softmax: 2 threads per row, interleaved cols (stride 2) ---
        {
            int row  = tid >> 1;
            int part = tid & 1;
            float* srow = Ss + row * 68 + part;
            float mx = srow[0];
#pragma unroll
            for (int u = 1; u < 32; ++u) mx = fmaxf(mx, srow[2 * u]);
            mx = fmaxf(mx, __shfl_xor_sync(0xffffffffu, mx, 1));
            float m_old = m_s[row];
            float m_new = fmaxf(m_old, mx);
            float ps = 0.f;
#pragma unroll
            for (int u = 0; u < 32; ++u) {
                float p = __expf(srow[2 * u] - m_new);
                srow[2 * u] = rtf32(p);
                ps += p;
            }
            ps += __shfl_xor_sync(0xffffffffu, ps, 1);
            if (part == 0) {
                float fch = __expf(m_old - m_new);
                f_s[row] = fch;
                l_s[row] = l_s[row] * fch + ps;
                m_s[row] = m_new;
            }
        }
        __syncthreads();

        // --- rescale accumulator, then O += P @ V ---
#pragma unroll
        for (int i = 0; i < 2; ++i) {
            float f0 = f_s[wm + i * 16 + r];
            float f1 = f_s[wm + i * 16 + r + 8];
#pragma unroll
            for (int j = 0; j < 4; ++j) {
                oacc[i][j][0] *= f0; oacc[i][j][1] *= f0;
                oacc[i][j][2] *= f1; oacc[i][j][3] *= f1;
            }
        }
#pragma unroll
        for (int ks = 0; ks < 64; ks += 8) {
            uint32_t af[2][4];
#pragma unroll
            for (int i = 0; i < 2; ++i) {
                const float* p = Ss + (wm + i * 16 + r) * 68 + ks + c;
                af[i][0] = fu(p[0]);
                af[i][1] = fu(p[8 * 68]);
                af[i][2] = fu(p[4]);
                af[i][3] = fu(p[8 * 68 + 4]);
            }
#pragma unroll
            for (int j = 0; j < 4; ++j) {
                const float* p = Vs + (ks + c) * 72 + wn + j * 8 + r;
                uint32_t bf[2] = { fu(p[0]), fu(p[4 * 72]) };
#pragma unroll
                for (int i = 0; i < 2; ++i) mma8(oacc[i][j], af[i], bf);
            }
        }
    }

    // Epilogue: normalize, head-mask, tf32-round, write [B,S,HID]
    const int bix = bh >> 4;
    const int h   = bh & 15;
    const float mask = head_mask[h];
#pragma unroll
    for (int i = 0; i < 2; ++i) {
        int rr = wm + i * 16 + r;
        float inv0 = mask / l_s[rr];
        float inv1 = mask / l_s[rr + 8];
        int s = s0 + rr;
#pragma unroll
        for (int j = 0; j < 4; ++j) {
            int dd = wn + j * 8 + 2 * c;
            float* p = g_ctx + ((size_t)bix * S_ + s) * HID + h * 64 + dd;
            *(float2*)p = make_float2(rtf32(oacc[i][j][0] * inv0),
                                      rtf32(oacc[i][j][1] * inv0));
            *(float2*)(p + 8 * HID) = make_float2(rtf32(oacc[i][j][2] * inv1),
                                                  rtf32(oacc[i][j][3] * inv1));
        }
    }
}

// ---------------------------------------------------------------------------
extern "C" void kernel_launch(void* const* d_in, const int* in_sizes, int n_in,
                              void* d_out, int out_size)
{
    const float* x  = (const float*)d_in[0];
    const float* Wq = (const float*)d_in[1];
    const float* bq = (const float*)d_in[2];
    const float* Wk = (const float*)d_in[3];
    const float* bk = (const float*)d_in[4];
    const float* Wv = (const float*)d_in[5];
    const float* bv = (const float*)d_in[6];
    const float* Wo = (const float*)d_in[7];
    const float* bo = (const float*)d_in[8];
    const float* head_mask = (const float*)d_in[9];
    float* out = (float*)d_out;

    static bool attr_set = false;
    if (!attr_set) {
        cudaFuncSetAttribute(proj_tc, cudaFuncAttributeMaxDynamicSharedMemorySize, PROJ_SMEM);
        cudaFuncSetAttribute(attn_tc, cudaFuncAttributeMaxDynamicSharedMemorySize, ATTN_SMEM);
        attr_set = true;
    }

    // Round inputs to tf32 (RNA)
    const int xn4 = B_ * S_ * HID / 4;
    const int wn4 = HID * HID / 4;
    round_k<<<(xn4 + 255) / 256, 256>>>((const float4*)x,  0, xn4);
    round_k<<<(wn4 + 255) / 256, 256>>>((const float4*)Wq, 1, wn4);
    round_k<<<(wn4 + 255) / 256, 256>>>((const float4*)Wk, 2, wn4);
    round_k<<<(wn4 + 255) / 256, 256>>>((const float4*)Wv, 3, wn4);
    round_k<<<(wn4 + 255) / 256, 256>>>((const float4*)Wo, 4, wn4);

    // QKV projection: 12 x 64 blocks of 128m x 256n
    float* xr_dev;  cudaGetSymbolAddress((void**)&xr_dev,  g_xr);
    float* ctx_dev; cudaGetSymbolAddress((void**)&ctx_dev, g_ctx);
    proj_tc<<<dim3(12, 64), 256, PROJ_SMEM>>>(xr_dev, 0, bq, bk, bv, bo, nullptr);

    // Attention: 16 q-tiles x 64 bh
    attn_tc<<<dim3(16, 64), 256, ATTN_SMEM>>>(head_mask);

    // O projection: 4 x 64
    proj_tc<<<dim3(4, 64), 256, PROJ_SMEM>>>(ctx_dev, 1, bq, bk, bv, bo, out);
}

// round 5
// speedup vs baseline: 4.0095x; 1.2888x over previous
#include <cuda_runtime.h>
#include <cstdint>

#define B_ 4
#define S_ 2048
#define H_ 16
#define D_ 64
#define HID 1024
#define BH_ (B_ * H_)

// ---------------------------------------------------------------------------
// Device scratch (allocation-free rule)
// ---------------------------------------------------------------------------
__device__ float g_q[(size_t)BH_ * S_ * D_];    // [B,H,S,D] tf32-rounded
__device__ float g_k[(size_t)BH_ * S_ * D_];
__device__ float g_v[(size_t)BH_ * S_ * D_];
__device__ float g_ctx[(size_t)B_ * S_ * HID];  // [B,S,HID] tf32-rounded
__device__ float g_xr[(size_t)B_ * S_ * HID];   // x rounded to tf32
__device__ float g_wr[4 * (size_t)HID * HID];   // Wq|Wk|Wv|Wo rounded to tf32

// ---------------------------------------------------------------------------
// Helpers
// ---------------------------------------------------------------------------
__device__ __forceinline__ float rtf32(float x) {
    uint32_t u;
    asm("cvt.rna.tf32.f32 %0, %1;" : "=r"(u) : "f"(x));
    return __uint_as_float(u);
}
__device__ __forceinline__ float ex2(float x) {
    float y;
    asm("ex2.approx.f32 %0, %1;" : "=f"(y) : "f"(x));
    return y;
}
__device__ __forceinline__ uint32_t fu(float x) { return __float_as_uint(x); }

// mma.sync m16n8k8 tf32, fp32 accumulate
__device__ __forceinline__ void mma8(float* d, const uint32_t* a, const uint32_t* b) {
    asm volatile(
        "mma.sync.aligned.m16n8k8.row.col.f32.tf32.tf32.f32 "
        "{%0,%1,%2,%3}, {%4,%5,%6,%7}, {%8,%9}, {%0,%1,%2,%3};"
        : "+f"(d[0]), "+f"(d[1]), "+f"(d[2]), "+f"(d[3])
        : "r"(a[0]), "r"(a[1]), "r"(a[2]), "r"(a[3]), "r"(b[0]), "r"(b[1]));
}

__device__ __forceinline__ uint32_t smem_u32(const void* p) {
    uint32_t a;
    asm("{ .reg .u64 t; cvta.to.shared.u64 t, %1; cvt.u32.u64 %0, t; }"
        : "=r"(a) : "l"(p));
    return a;
}
__device__ __forceinline__ void cpa16(uint32_t s, const void* g) {
    asm volatile("cp.async.cg.shared.global [%0], [%1], 16;" :: "r"(s), "l"(g));
}
__device__ __forceinline__ void cpa_commit() {
    asm volatile("cp.async.commit_group;" ::: "memory");
}
template <int N> __device__ __forceinline__ void cpa_wait() {
    asm volatile("cp.async.wait_group %0;" :: "n"(N) : "memory");
}

// ---------------------------------------------------------------------------
// Round inputs to tf32 (RNA; HW MMA path truncates -> biased)
// which: 0 -> g_xr, 1..4 -> g_wr quadrant (Wq,Wk,Wv,Wo)
// ---------------------------------------------------------------------------
__global__ void round_k(const float4* __restrict__ src, int which, int n4)
{
    int i = blockIdx.x * blockDim.x + threadIdx.x;
    if (i >= n4) return;
    float4* dst = (which == 0) ? (float4*)g_xr
                               : (float4*)(g_wr + (size_t)(which - 1) * HID * HID);
    float4 v = src[i];
    v.x = rtf32(v.x); v.y = rtf32(v.y); v.z = rtf32(v.z); v.w = rtf32(v.w);
    dst[i] = v;
}

// ---------------------------------------------------------------------------
// Projection GEMM on mma.sync tf32.  C[m,n] = A[m,:] . W[n,:] + bias[n]
// 128m x 256n block, BK=16, 256 threads (8 warps, warp 64x64).
// 4-stage cp.async pipeline, one __syncthreads per slab.
// ---------------------------------------------------------------------------
#define PJ_AS (128 * 20)
#define PJ_BS (256 * 20)
static constexpr int PROJ_SMEM = 4 * (PJ_AS + PJ_BS) * 4;  // 122880 B

__global__ __launch_bounds__(256, 1) void proj_tc(
    const float* __restrict__ Aall, int mode,
    const float* __restrict__ bq, const float* __restrict__ bk,
    const float* __restrict__ bv, const float* __restrict__ bo,
    float* __restrict__ outflat)
{
    extern __shared__ float sm[];
    float* As = sm;                 // [4][128*20]
    float* Bs = sm + 4 * PJ_AS;     // [4][256*20]

    const int tid = threadIdx.x;
    const int m0  = blockIdx.y * 128;

    int which, n0g;
    const float* bias;
    if (mode == 0) {
        which = blockIdx.x >> 2;             // 0=Q 1=K 2=V
        n0g   = (blockIdx.x & 3) * 256;
        bias  = (which == 0) ? bq : (which == 1) ? bk : bv;
    } else {
        which = 3;
        n0g   = blockIdx.x * 256;
        bias  = bo;
    }
    const float* Wb = g_wr + (size_t)which * HID * HID + (size_t)n0g * HID;
    const float* Ab = Aall + (size_t)m0 * HID;

    const uint32_t sb = smem_u32(sm);

    auto load_slab = [&](int kt) {
        const int bi = kt & 3;
        const uint32_t abase = sb + (uint32_t)(bi * PJ_AS) * 4u;
        const uint32_t bbase = sb + (uint32_t)(4 * PJ_AS + bi * PJ_BS) * 4u;
        const int k0 = kt * 16;
#pragma unroll
        for (int it = 0; it < 2; ++it) {
            int f = tid + it * 256;
            int row = f >> 2, kq = (f & 3) * 4;
            cpa16(abase + (uint32_t)(row * 20 + kq) * 4u,
                  Ab + (size_t)row * HID + k0 + kq);
        }
#pragma unroll
        for (int it = 0; it < 4; ++it) {
            int f = tid + it * 256;
            int row = f >> 2, kq = (f & 3) * 4;
            cpa16(bbase + (uint32_t)(row * 20 + kq) * 4u,
                  Wb + (size_t)row * HID + k0 + kq);
        }
        cpa_commit();
    };

    const int w    = tid >> 5;
    const int lane = tid & 31;
    const int r    = lane >> 2;
    const int c    = lane & 3;
    const int wm   = (w & 1) * 64;
    const int wn   = (w >> 1) * 64;

    float acc[4][8][4];
#pragma unroll
    for (int i = 0; i < 4; ++i)
#pragma unroll
        for (int j = 0; j < 8; ++j)
#pragma unroll
            for (int q = 0; q < 4; ++q) acc[i][j][q] = 0.f;

    load_slab(0);
    load_slab(1);
    load_slab(2);

    for (int kt = 0; kt < 64; ++kt) {
        cpa_wait<2>();          // slab kt resident (FIFO group completion)
        __syncthreads();        // all warps done reading buffer (kt-1)&3
        if (kt + 3 < 64) load_slab(kt + 3);
        else cpa_commit();      // keep group count uniform for wait<2>

        const float* as = As + (kt & 3) * PJ_AS + (wm + r) * 20;
        const float* bs = Bs + (kt & 3) * PJ_BS + (wn + r) * 20;   // FIX: no double 4*PJ_AS

#pragma unroll
        for (int ks = 0; ks < 16; ks += 8) {
            uint32_t af[4][4];
#pragma unroll
            for (int i = 0; i < 4; ++i) {
                const float* p = as + i * 16 * 20 + ks + c;
                af[i][0] = fu(p[0]);
                af[i][1] = fu(p[8 * 20]);
                af[i][2] = fu(p[4]);
                af[i][3] = fu(p[8 * 20 + 4]);
            }
#pragma unroll
            for (int j = 0; j < 8; ++j) {
                const float* p = bs + j * 8 * 20 + ks + c;
                uint32_t bf[2] = { fu(p[0]), fu(p[4]) };
#pragma unroll
                for (int i = 0; i < 4; ++i) mma8(acc[i][j], af[i], bf);
            }
        }
    }

    // Epilogue
    if (mode == 0) {
        float* dst = (which == 0) ? g_q : (which == 1) ? g_k : g_v;
#pragma unroll
        for (int j = 0; j < 8; ++j) {
            const int nl = n0g + wn + j * 8 + 2 * c;
            const float b0 = bias[nl], b1 = bias[nl + 1];
            const int h  = nl >> 6;
            const int dd = nl & 63;
#pragma unroll
            for (int i = 0; i < 4; ++i) {
                int m = m0 + wm + i * 16 + r;
                int bi = m >> 11, s = m & 2047;
                float* p = dst + (((size_t)(bi * H_ + h) * S_ + s) * D_ + dd);
                *(float2*)p = make_float2(rtf32(acc[i][j][0] + b0),
                                          rtf32(acc[i][j][1] + b1));
                *(float2*)(p + 8 * D_) = make_float2(rtf32(acc[i][j][2] + b0),
                                                     rtf32(acc[i][j][3] + b1));
            }
        }
    } else {
#pragma unroll
        for (int j = 0; j < 8; ++j) {
            const int n = n0g + wn + j * 8 + 2 * c;
            const float b0 = bias[n], b1 = bias[n + 1];
#pragma unroll
            for (int i = 0; i < 4; ++i) {
                int m = m0 + wm + i * 16 + r;
                float* p = outflat + (size_t)m * HID + n;
                *(float2*)p = make_float2(acc[i][j][0] + b0, acc[i][j][1] + b1);
                *(float2*)(p + 8 * HID) =
                    make_float2(acc[i][j][2] + b0, acc[i][j][3] + b1);
            }
        }
    }
}

// ---------------------------------------------------------------------------
// Flash attention, register-resident softmax.
// Block = 128 q-rows x one bh, 256 threads = 8 warps, warp tile 16q x 64k.
// Q fragments persist in registers across all key tiles. P never touches smem:
// V rows are stored permuted (u -> (u>>1)|((u&1)<<2) within each 8-row group)
// so the QK accumulator fragment IS the PV A fragment (register rename).
// K/V double-buffered via cp.async; 1 __syncthreads per key tile.
// ---------------------------------------------------------------------------
#define AT_KST 68
#define AT_VST 72
static constexpr int ATTN_SMEM = (2 * 64 * AT_KST + 2 * 64 * AT_VST) * 4;  // 71680

__global__ __launch_bounds__(256, 1) void attn_tc(const float* __restrict__ head_mask)
{
    extern __shared__ float sm[];
    float* Ks = sm;                      // [2][64*68]
    float* Vs = sm + 2 * 64 * AT_KST;    // [2][64*72]

    const int tid = threadIdx.x;
    const int bh  = blockIdx.y;
    const int s0  = blockIdx.x * 128;

    const float* Q = g_q + (size_t)bh * S_ * D_;
    const float* K = g_k + (size_t)bh * S_ * D_;
    const float* V = g_v + (size_t)bh * S_ * D_;

    const int w    = tid >> 5;
    const int lane = tid & 31;
    const int r    = lane >> 2;
    const int c    = lane & 3;
    const int wm   = w * 16;

    const uint32_t sb = smem_u32(sm);

    // Q fragments: scale by 1/8 * log2(e) (exp -> ex2), RNA-round to tf32.
    const float SC = 0.125f * 1.4426950408889634f;
    uint32_t qf[8][4];
    {
        const float* q0 = Q + (size_t)(s0 + wm + r) * D_;
        const float* q1 = q0 + 8 * D_;
#pragma unroll
        for (int ks = 0; ks < 8; ++ks) {
            qf[ks][0] = fu(rtf32(q0[8 * ks + c] * SC));
            qf[ks][1] = fu(rtf32(q1[8 * ks + c] * SC));
            qf[ks][2] = fu(rtf32(q0[8 * ks + c + 4] * SC));
            qf[ks][3] = fu(rtf32(q1[8 * ks + c + 4] * SC));
        }
    }

    auto load_tile = [&](int kt) {
        const int bi = kt & 1;
        const uint32_t kd = sb + (uint32_t)(bi * 64 * AT_KST) * 4u;
        const uint32_t vd = sb + (uint32_t)((2 * 64 * AT_KST) + bi * 64 * AT_VST) * 4u;
#pragma unroll
        for (int it = 0; it < 4; ++it) {
            int f = tid + it * 256;          // 0..1023
            int row = f >> 4;
            int dq  = (f & 15) * 4;
            cpa16(kd + (uint32_t)(row * AT_KST + dq) * 4u,
                  K + (size_t)(kt * 64 + row) * D_ + dq);
            int u  = row & 7;
            int pr = (row & ~7) | ((u >> 1) | ((u & 1) << 2));
            cpa16(vd + (uint32_t)(pr * AT_VST + dq) * 4u,
                  V + (size_t)(kt * 64 + row) * D_ + dq);
        }
        cpa_commit();
    };

    float m0 = -1e30f, m1 = -1e30f, l0 = 0.f, l1 = 0.f;
    float oacc[8][4];
#pragma unroll
    for (int j = 0; j < 8; ++j)
#pragma unroll
        for (int q = 0; q < 4; ++q) oacc[j][q] = 0.f;

    load_tile(0);

    for (int kt = 0; kt < S_ / 64; ++kt) {
        cpa_wait<0>();
        __syncthreads();
        if (kt + 1 < S_ / 64) load_tile(kt + 1);

        const float* ks_ = Ks + (kt & 1) * 64 * AT_KST;
        const float* vs_ = Vs + (kt & 1) * 64 * AT_VST;

        // --- S = Q @ K^T (scaled, log2e space) ---
        float sacc[8][4];
#pragma unroll
        for (int j = 0; j < 8; ++j)
#pragma unroll
            for (int q = 0; q < 4; ++q) sacc[j][q] = 0.f;

#pragma unroll
        for (int ksb = 0; ksb < 8; ++ksb) {
#pragma unroll
            for (int j = 0; j < 8; ++j) {
                const float* p = ks_ + (8 * j + r) * AT_KST + 8 * ksb + c;
                uint32_t bf[2] = { fu(p[0]), fu(p[4]) };
                mma8(sacc[j], qf[ksb], bf);
            }
        }

        // --- register softmax (rows r and r+8 of this warp's 16) ---
        float mx0 = sacc[0][0], mx1 = sacc[0][2];
#pragma unroll
        for (int j = 0; j < 8; ++j) {
            mx0 = fmaxf(mx0, fmaxf(sacc[j][0], sacc[j][1]));
            mx1 = fmaxf(mx1, fmaxf(sacc[j][2], sacc[j][3]));
        }
        mx0 = fmaxf(mx0, __shfl_xor_sync(0xffffffffu, mx0, 1));
        mx0 = fmaxf(mx0, __shfl_xor_sync(0xffffffffu, mx0, 2));
        mx1 = fmaxf(mx1, __shfl_xor_sync(0xffffffffu, mx1, 1));
        mx1 = fmaxf(mx1, __shfl_xor_sync(0xffffffffu, mx1, 2));

        const float nm0 = fmaxf(m0, mx0);
        const float nm1 = fmaxf(m1, mx1);
        const float f0 = ex2(m0 - nm0);
        const float f1 = ex2(m1 - nm1);

        float ps0 = 0.f, ps1 = 0.f;
#pragma unroll
        for (int j = 0; j < 8; ++j) {
            float p0 = rtf32(ex2(sacc[j][0] - nm0));
            float p1 = rtf32(ex2(sacc[j][1] - nm0));
            float p2 = rtf32(ex2(sacc[j][2] - nm1));
            float p3 = rtf32(ex2(sacc[j][3] - nm1));
            sacc[j][0] = p0; sacc[j][1] = p1; sacc[j][2] = p2; sacc[j][3] = p3;
            ps0 += p0 + p1;
            ps1 += p2 + p3;
        }
        ps0 += __shfl_xor_sync(0xffffffffu, ps0, 1);
        ps0 += __shfl_xor_sync(0xffffffffu, ps0, 2);
        ps1 += __shfl_xor_sync(0xffffffffu, ps1, 1);
        ps1 += __shfl_xor_sync(0xffffffffu, ps1, 2);

        l0 = l0 * f0 + ps0;
        l1 = l1 * f1 + ps1;
        m0 = nm0; m1 = nm1;

        // --- O = O*f + P @ V (P fragments = renamed sacc; V row-permuted) ---
#pragma unroll
        for (int j = 0; j < 8; ++j) {
            oacc[j][0] *= f0; oacc[j][1] *= f0;
            oacc[j][2] *= f1; oacc[j][3] *= f1;
        }
#pragma unroll
        for (int t = 0; t < 8; ++t) {
            uint32_t af[4] = { fu(sacc[t][0]), fu(sacc[t][2]),
                               fu(sacc[t][1]), fu(sacc[t][3]) };
#pragma unroll
            for (int j = 0; j < 8; ++j) {
                const float* p = vs_ + (8 * t + c) * AT_VST + 8 * j + r;
                uint32_t bf[2] = { fu(p[0]), fu(p[4 * AT_VST]) };
                mma8(oacc[j], af, bf);
            }
        }
    }

    // Epilogue: normalize, head-mask, tf32-round, write [B,S,HID]
    const int bix = bh >> 4;
    const int h   = bh & 15;
    const float mask = head_mask[h];
    const float inv0 = mask / l0;
    const float inv1 = mask / l1;
    const int s = s0 + wm + r;
#pragma unroll
    for (int j = 0; j < 8; ++j) {
        int dd = 8 * j + 2 * c;
        float* p = g_ctx + ((size_t)bix * S_ + s) * HID + h * 64 + dd;
        *(float2*)p = make_float2(rtf32(oacc[j][0] * inv0),
                                  rtf32(oacc[j][1] * inv0));
        *(float2*)(p + 8 * HID) = make_float2(rtf32(oacc[j][2] * inv1),
                                              rtf32(oacc[j][3] * inv1));
    }
}

// ---------------------------------------------------------------------------
extern "C" void kernel_launch(void* const* d_in, const int* in_sizes, int n_in,
                              void* d_out, int out_size)
{
    const float* x  = (const float*)d_in[0];
    const float* Wq = (const float*)d_in[1];
    const float* bq = (const float*)d_in[2];
    const float* Wk = (const float*)d_in[3];
    const float* bk = (const float*)d_in[4];
    const float* Wv = (const float*)d_in[5];
    const float* bv = (const float*)d_in[6];
    const float* Wo = (const float*)d_in[7];
    const float* bo = (const float*)d_in[8];
    const float* head_mask = (const float*)d_in[9];
    float* out = (float*)d_out;

    static bool attr_set = false;
    if (!attr_set) {
        cudaFuncSetAttribute(proj_tc, cudaFuncAttributeMaxDynamicSharedMemorySize, PROJ_SMEM);
        cudaFuncSetAttribute(attn_tc, cudaFuncAttributeMaxDynamicSharedMemorySize, ATTN_SMEM);
        attr_set = true;
    }

    // Round inputs to tf32 (RNA)
    const int xn4 = B_ * S_ * HID / 4;
    const int wn4 = HID * HID / 4;
    round_k<<<(xn4 + 255) / 256, 256>>>((const float4*)x,  0, xn4);
    round_k<<<(wn4 + 255) / 256, 256>>>((const float4*)Wq, 1, wn4);
    round_k<<<(wn4 + 255) / 256, 256>>>((const float4*)Wk, 2, wn4);
    round_k<<<(wn4 + 255) / 256, 256>>>((const float4*)Wv, 3, wn4);
    round_k<<<(wn4 + 255) / 256, 256>>>((const float4*)Wo, 4, wn4);

    float* xr_dev;  cudaGetSymbolAddress((void**)&xr_dev,  g_xr);
    float* ctx_dev; cudaGetSymbolAddress((void**)&ctx_dev, g_ctx);

    // QKV projection: 12 x 64 blocks of 128m x 256n
    proj_tc<<<dim3(12, 64), 256, PROJ_SMEM>>>(xr_dev, 0, bq, bk, bv, bo, nullptr);

    // Attention: 16 q-tiles x 64 bh
    attn_tc<<<dim3(16, 64), 256, ATTN_SMEM>>>(head_mask);

    // O projection: 4 x 64
    proj_tc<<<dim3(4, 64), 256, PROJ_SMEM>>>(ctx_dev, 1, bq, bk, bv, bo, out);
}

// round 6
// speedup vs baseline: 7.5527x; 1.8837x over previous
#include <cuda_runtime.h>
#include <cuda_fp16.h>
#include <cstdint>

#define B_ 4
#define S_ 2048
#define H_ 16
#define D_ 64
#define HID 1024
#define BH_ (B_ * H_)

// ---------------------------------------------------------------------------
// Device scratch (allocation-free rule). All fp16.
// ---------------------------------------------------------------------------
__device__ __align__(16) __half g_qh[(size_t)BH_ * S_ * D_];   // [B,H,S,D], pre-scaled by 1/8*log2e
__device__ __align__(16) __half g_kh[(size_t)BH_ * S_ * D_];   // [B,H,S,D]
__device__ __align__(16) __half g_vt[(size_t)BH_ * D_ * S_];   // [B,H,D,S]  (transposed!)
__device__ __align__(16) __half g_ctxh[(size_t)B_ * S_ * HID]; // [B,S,HID]
__device__ __align__(16) __half g_xh[(size_t)B_ * S_ * HID];   // x in fp16
__device__ __align__(16) __half g_wh[4 * (size_t)HID * HID];   // Wq|Wk|Wv|Wo fp16

// ---------------------------------------------------------------------------
// Helpers
// ---------------------------------------------------------------------------
__device__ __forceinline__ float ex2(float x) {
    float y;
    asm("ex2.approx.f32 %0, %1;" : "=f"(y) : "f"(x));
    return y;
}
// pack two floats -> half2 (lo = first arg)
__device__ __forceinline__ uint32_t h2u(float lo, float hi) {
    uint32_t d;
    asm("cvt.rn.f16x2.f32 %0, %1, %2;" : "=r"(d) : "f"(hi), "f"(lo));
    return d;
}

// mma.sync m16n8k16 fp16 inputs, fp32 accumulate (sm_80+, legal at compute_103)
__device__ __forceinline__ void mma16(float* d, const uint32_t* a, const uint32_t* b) {
    asm volatile(
        "mma.sync.aligned.m16n8k16.row.col.f32.f16.f16.f32 "
        "{%0,%1,%2,%3}, {%4,%5,%6,%7}, {%8,%9}, {%0,%1,%2,%3};"
        : "+f"(d[0]), "+f"(d[1]), "+f"(d[2]), "+f"(d[3])
        : "r"(a[0]), "r"(a[1]), "r"(a[2]), "r"(a[3]), "r"(b[0]), "r"(b[1]));
}

__device__ __forceinline__ uint32_t smem_u32(const void* p) {
    uint32_t a;
    asm("{ .reg .u64 t; cvta.to.shared.u64 t, %1; cvt.u32.u64 %0, t; }"
        : "=r"(a) : "l"(p));
    return a;
}
__device__ __forceinline__ void cpa16(uint32_t s, const void* g) {
    asm volatile("cp.async.cg.shared.global [%0], [%1], 16;" :: "r"(s), "l"(g));
}
__device__ __forceinline__ void cpa_commit() {
    asm volatile("cp.async.commit_group;" ::: "memory");
}
template <int N> __device__ __forceinline__ void cpa_wait() {
    asm volatile("cp.async.wait_group %0;" :: "n"(N) : "memory");
}

// ---------------------------------------------------------------------------
// fp32 -> fp16 conversion kernels
// ---------------------------------------------------------------------------
__global__ void cvt_x(const float4* __restrict__ src, int n4)
{
    int i = blockIdx.x * blockDim.x + threadIdx.x;
    if (i >= n4) return;
    float4 v = src[i];
    uint2 o = make_uint2(h2u(v.x, v.y), h2u(v.z, v.w));
    ((uint2*)g_xh)[i] = o;
}

__global__ void cvt_w(const float4* __restrict__ wq, const float4* __restrict__ wk,
                      const float4* __restrict__ wv, const float4* __restrict__ wo)
{
    int i = blockIdx.x * blockDim.x + threadIdx.x;   // 0 .. 4*262144-1
    const int per = HID * HID / 4;                   // 262144
    int which = i / per;
    int local = i - which * per;
    const float4* src = (which == 0) ? wq : (which == 1) ? wk : (which == 2) ? wv : wo;
    float4 v = src[local];
    ((uint2*)g_wh)[i] = make_uint2(h2u(v.x, v.y), h2u(v.z, v.w));
}

// ---------------------------------------------------------------------------
// Projection GEMM on mma.sync fp16.  C[m,n] = A[m,:] . W[n,:] + bias[n]
// 128m x 256n block, BK=32 halves, 256 threads (8 warps, warp 64x64).
// 4-stage cp.async pipeline. Smem rows = 16 half2 + 4 pad = 20 u32
// (20*r + c distinct mod 32 -> conflict-free fragments).
// mode 0: QKV. Q scaled by 1/8*log2e; V written transposed [B,H,D,S].
// mode 1: O-proj, fp32 output + bias.
// ---------------------------------------------------------------------------
#define PJ_A32 (128 * 20)
#define PJ_B32 (256 * 20)
static constexpr int PROJ_SMEM = 4 * (PJ_A32 + PJ_B32) * 4;  // 122880 B

__global__ __launch_bounds__(256, 1) void proj_tc(
    const __half* __restrict__ Aall, int mode,
    const float* __restrict__ bq, const float* __restrict__ bk,
    const float* __restrict__ bv, const float* __restrict__ bo,
    float* __restrict__ outflat)
{
    extern __shared__ uint32_t smu[];
    uint32_t* As = smu;                 // [4][128*20]
    uint32_t* Bs = smu + 4 * PJ_A32;    // [4][256*20]

    const int tid = threadIdx.x;
    const int m0  = blockIdx.y * 128;

    int which, n0g;
    const float* bias;
    if (mode == 0) {
        which = blockIdx.x >> 2;             // 0=Q 1=K 2=V
        n0g   = (blockIdx.x & 3) * 256;
        bias  = (which == 0) ? bq : (which == 1) ? bk : bv;
    } else {
        which = 3;
        n0g   = blockIdx.x * 256;
        bias  = bo;
    }
    const __half* Wb = g_wh + (size_t)which * HID * HID + (size_t)n0g * HID;
    const __half* Ab = Aall + (size_t)m0 * HID;

    const uint32_t sb = smem_u32(smu);

    auto load_slab = [&](int kt) {
        const int bi = kt & 3;
        const uint32_t abase = sb + (uint32_t)(bi * PJ_A32) * 4u;
        const uint32_t bbase = sb + (uint32_t)(4 * PJ_A32 + bi * PJ_B32) * 4u;
        const int k0 = kt * 32;
        // A: 128 rows x 32 halves = 512 x 16B
#pragma unroll
        for (int it = 0; it < 2; ++it) {
            int f = tid + it * 256;
            int row = f >> 2, kq = (f & 3) * 8;        // halves
            cpa16(abase + (uint32_t)(row * 20 + (f & 3) * 4) * 4u,
                  Ab + (size_t)row * HID + k0 + kq);
        }
        // B: 256 rows x 32 halves = 1024 x 16B
#pragma unroll
        for (int it = 0; it < 4; ++it) {
            int f = tid + it * 256;
            int row = f >> 2, kq = (f & 3) * 8;
            cpa16(bbase + (uint32_t)(row * 20 + (f & 3) * 4) * 4u,
                  Wb + (size_t)row * HID + k0 + kq);
        }
        cpa_commit();
    };

    const int w    = tid >> 5;
    const int lane = tid & 31;
    const int r    = lane >> 2;
    const int c    = lane & 3;
    const int wm   = (w & 1) * 64;
    const int wn   = (w >> 1) * 64;

    float acc[4][8][4];
#pragma unroll
    for (int i = 0; i < 4; ++i)
#pragma unroll
        for (int j = 0; j < 8; ++j)
#pragma unroll
            for (int q = 0; q < 4; ++q) acc[i][j][q] = 0.f;

    load_slab(0);
    load_slab(1);
    load_slab(2);

    for (int kt = 0; kt < 32; ++kt) {
        cpa_wait<2>();
        __syncthreads();
        if (kt + 3 < 32) load_slab(kt + 3);
        else cpa_commit();

        const uint32_t* as = As + (kt & 3) * PJ_A32 + (wm + r) * 20;
        const uint32_t* bs = Bs + (kt & 3) * PJ_B32 + (wn + r) * 20;

#pragma unroll
        for (int ks = 0; ks < 2; ++ks) {
            uint32_t af[4][4];
#pragma unroll
            for (int i = 0; i < 4; ++i) {
                const uint32_t* p = as + i * 320 + ks * 8 + c;
                af[i][0] = p[0];
                af[i][1] = p[160];      // row +8
                af[i][2] = p[4];        // k  +8
                af[i][3] = p[164];
            }
#pragma unroll
            for (int j = 0; j < 8; ++j) {
                const uint32_t* p = bs + j * 160 + ks * 8 + c;
                uint32_t bf[2] = { p[0], p[4] };
#pragma unroll
                for (int i = 0; i < 4; ++i) mma16(acc[i][j], af[i], bf);
            }
        }
    }

    // Epilogue
    if (mode == 0) {
        const float SCQ = 0.125f * 1.4426950408889634f;   // fold 1/sqrt(D)*log2e into Q
#pragma unroll
        for (int j = 0; j < 8; ++j) {
            const int nl = n0g + wn + j * 8 + 2 * c;      // [0,1024)
            const float b0 = bias[nl], b1 = bias[nl + 1];
            const int h  = nl >> 6;
            const int dd = nl & 63;
#pragma unroll
            for (int i = 0; i < 4; ++i) {
                int m = m0 + wm + i * 16 + r;
                int bi = m >> 11, s = m & 2047;
                float v0 = acc[i][j][0] + b0, v1 = acc[i][j][1] + b1;
                float v2 = acc[i][j][2] + b0, v3 = acc[i][j][3] + b1;
                if (which == 0) {
                    __half* p = g_qh + (((size_t)(bi * H_ + h) * S_ + s) * D_ + dd);
                    *(uint32_t*)p = h2u(v0 * SCQ, v1 * SCQ);
                    *(uint32_t*)(p + 8 * D_) = h2u(v2 * SCQ, v3 * SCQ);
                } else if (which == 1) {
                    __half* p = g_kh + (((size_t)(bi * H_ + h) * S_ + s) * D_ + dd);
                    *(uint32_t*)p = h2u(v0, v1);
                    *(uint32_t*)(p + 8 * D_) = h2u(v2, v3);
                } else {
                    // V transposed: [B,H,D,S]
                    __half* p = g_vt + (((size_t)(bi * H_ + h) * D_ + dd) * S_ + s);
                    p[0]      = __float2half_rn(v0);
                    p[S_]     = __float2half_rn(v1);
                    p[8]      = __float2half_rn(v2);
                    p[S_ + 8] = __float2half_rn(v3);
                }
            }
        }
    } else {
#pragma unroll
        for (int j = 0; j < 8; ++j) {
            const int n = n0g + wn + j * 8 + 2 * c;
            const float b0 = bias[n], b1 = bias[n + 1];
#pragma unroll
            for (int i = 0; i < 4; ++i) {
                int m = m0 + wm + i * 16 + r;
                float* p = outflat + (size_t)m * HID + n;
                *(float2*)p = make_float2(acc[i][j][0] + b0, acc[i][j][1] + b1);
                *(float2*)(p + 8 * HID) =
                    make_float2(acc[i][j][2] + b0, acc[i][j][3] + b1);
            }
        }
    }
}

// ---------------------------------------------------------------------------
// Flash attention on fp16 mma. Block = 128 q x one bh, 8 warps (16q x 64k each).
// QK accumulator pairs pack directly into PV A fragments (cvt.rn.f16x2) —
// no smem round-trip, no permutation. V is [B,H,D,S] so PV B frags are u32.
// Smem rows: 32 half2 + 4 pad = 36 u32 (36≡4 mod 32 -> conflict-free).
// ---------------------------------------------------------------------------
#define AT_ST 36
#define AT_TILE (64 * AT_ST)          // u32 per K or V stage
static constexpr int ATTN_SMEM = 4 * AT_TILE * 4;   // 36864 B

__global__ __launch_bounds__(256, 1) void attn_tc(const float* __restrict__ head_mask)
{
    extern __shared__ uint32_t smu[];
    uint32_t* Ks = smu;                  // [2][64*36]
    uint32_t* Vs = smu + 2 * AT_TILE;    // [2][64*36]

    const int tid = threadIdx.x;
    const int bh  = blockIdx.y;
    const int s0  = blockIdx.x * 128;

    const __half* K = g_kh + (size_t)bh * S_ * D_;
    const __half* V = g_vt + (size_t)bh * D_ * S_;

    const int w    = tid >> 5;
    const int lane = tid & 31;
    const int r    = lane >> 2;
    const int c    = lane & 3;
    const int wm   = w * 16;

    const uint32_t sb = smem_u32(smu);

    // Q fragments from gmem (already fp16, pre-scaled). 32 u32 per row.
    uint32_t qf[4][4];
    {
        const uint32_t* Qp = (const uint32_t*)(g_qh + (size_t)bh * S_ * D_);
        const uint32_t* q0 = Qp + (size_t)(s0 + wm + r) * 32;
        const uint32_t* q1 = q0 + 8 * 32;
#pragma unroll
        for (int ks = 0; ks < 4; ++ks) {
            qf[ks][0] = q0[ks * 8 + c];
            qf[ks][1] = q1[ks * 8 + c];
            qf[ks][2] = q0[ks * 8 + c + 4];
            qf[ks][3] = q1[ks * 8 + c + 4];
        }
    }

    auto load_tile = [&](int kt) {
        const int bi = kt & 1;
        const uint32_t kd = sb + (uint32_t)(bi * AT_TILE) * 4u;
        const uint32_t vd = sb + (uint32_t)((2 + bi) * AT_TILE) * 4u;
#pragma unroll
        for (int it = 0; it < 2; ++it) {
            int f = tid + it * 256;          // 0..511
            int row = f >> 3;
            int dq  = (f & 7) * 8;           // halves
            cpa16(kd + (uint32_t)(row * AT_ST + (f & 7) * 4) * 4u,
                  K + (size_t)(kt * 64 + row) * D_ + dq);
            cpa16(vd + (uint32_t)(row * AT_ST + (f & 7) * 4) * 4u,
                  V + (size_t)row * S_ + kt * 64 + dq);
        }
        cpa_commit();
    };

    float m0 = -1e30f, m1 = -1e30f, l0 = 0.f, l1 = 0.f;
    float oacc[8][4];
#pragma unroll
    for (int j = 0; j < 8; ++j)
#pragma unroll
        for (int q = 0; q < 4; ++q) oacc[j][q] = 0.f;

    load_tile(0);

    for (int kt = 0; kt < S_ / 64; ++kt) {
        cpa_wait<0>();
        __syncthreads();
        if (kt + 1 < S_ / 64) load_tile(kt + 1);

        const uint32_t* ks_ = Ks + (kt & 1) * AT_TILE;
        const uint32_t* vs_ = Vs + (kt & 1) * AT_TILE;

        // --- S = Q @ K^T (log2e space) ---
        float sacc[8][4];
#pragma unroll
        for (int j = 0; j < 8; ++j)
#pragma unroll
            for (int q = 0; q < 4; ++q) sacc[j][q] = 0.f;

#pragma unroll
        for (int ksb = 0; ksb < 4; ++ksb) {
#pragma unroll
            for (int j = 0; j < 8; ++j) {
                const uint32_t* p = ks_ + (8 * j + r) * AT_ST + 8 * ksb + c;
                uint32_t bf[2] = { p[0], p[4] };
                mma16(sacc[j], qf[ksb], bf);
            }
        }

        // --- register softmax (rows r, r+8 of this warp's 16) ---
        float mx0 = sacc[0][0], mx1 = sacc[0][2];
#pragma unroll
        for (int j = 0; j < 8; ++j) {
            mx0 = fmaxf(mx0, fmaxf(sacc[j][0], sacc[j][1]));
            mx1 = fmaxf(mx1, fmaxf(sacc[j][2], sacc[j][3]));
        }
        mx0 = fmaxf(mx0, __shfl_xor_sync(0xffffffffu, mx0, 1));
        mx0 = fmaxf(mx0, __shfl_xor_sync(0xffffffffu, mx0, 2));
        mx1 = fmaxf(mx1, __shfl_xor_sync(0xffffffffu, mx1, 1));
        mx1 = fmaxf(mx1, __shfl_xor_sync(0xffffffffu, mx1, 2));

        const float nm0 = fmaxf(m0, mx0);
        const float nm1 = fmaxf(m1, mx1);
        const float f0 = ex2(m0 - nm0);
        const float f1 = ex2(m1 - nm1);

        // exp + pack P fragments directly (fp16)
        uint32_t pf[4][4];
        float ps0 = 0.f, ps1 = 0.f;
#pragma unroll
        for (int t = 0; t < 4; ++t) {
            float p00 = ex2(sacc[2 * t][0] - nm0);
            float p01 = ex2(sacc[2 * t][1] - nm0);
            float p02 = ex2(sacc[2 * t][2] - nm1);
            float p03 = ex2(sacc[2 * t][3] - nm1);
            float p10 = ex2(sacc[2 * t + 1][0] - nm0);
            float p11 = ex2(sacc[2 * t + 1][1] - nm0);
            float p12 = ex2(sacc[2 * t + 1][2] - nm1);
            float p13 = ex2(sacc[2 * t + 1][3] - nm1);
            pf[t][0] = h2u(p00, p01);
            pf[t][1] = h2u(p02, p03);
            pf[t][2] = h2u(p10, p11);
            pf[t][3] = h2u(p12, p13);
            ps0 += (p00 + p01) + (p10 + p11);
            ps1 += (p02 + p03) + (p12 + p13);
        }
        ps0 += __shfl_xor_sync(0xffffffffu, ps0, 1);
        ps0 += __shfl_xor_sync(0xffffffffu, ps0, 2);
        ps1 += __shfl_xor_sync(0xffffffffu, ps1, 1);
        ps1 += __shfl_xor_sync(0xffffffffu, ps1, 2);

        l0 = l0 * f0 + ps0;
        l1 = l1 * f1 + ps1;
        m0 = nm0; m1 = nm1;

        // --- O = O*f + P @ V ---
#pragma unroll
        for (int j = 0; j < 8; ++j) {
            oacc[j][0] *= f0; oacc[j][1] *= f0;
            oacc[j][2] *= f1; oacc[j][3] *= f1;
        }
#pragma unroll
        for (int t = 0; t < 4; ++t) {
#pragma unroll
            for (int j = 0; j < 8; ++j) {
                const uint32_t* p = vs_ + (8 * j + r) * AT_ST + 8 * t + c;
                uint32_t bf[2] = { p[0], p[4] };
                mma16(oacc[j], pf[t], bf);
            }
        }
    }

    // Epilogue: normalize, head-mask, write ctx fp16 [B,S,HID]
    const int bix = bh >> 4;
    const int h   = bh & 15;
    const float mask = head_mask[h];
    const float inv0 = mask / l0;
    const float inv1 = mask / l1;
    const int s = s0 + wm + r;
#pragma unroll
    for (int j = 0; j < 8; ++j) {
        int dd = 8 * j + 2 * c;
        __half* p = g_ctxh + ((size_t)bix * S_ + s) * HID + h * 64 + dd;
        *(uint32_t*)p = h2u(oacc[j][0] * inv0, oacc[j][1] * inv0);
        *(uint32_t*)(p + 8 * HID) = h2u(oacc[j][2] * inv1, oacc[j][3] * inv1);
    }
}

// ---------------------------------------------------------------------------
extern "C" void kernel_launch(void* const* d_in, const int* in_sizes, int n_in,
                              void* d_out, int out_size)
{
    const float* x  = (const float*)d_in[0];
    const float* Wq = (const float*)d_in[1];
    const float* bq = (const float*)d_in[2];
    const float* Wk = (const float*)d_in[3];
    const float* bk = (const float*)d_in[4];
    const float* Wv = (const float*)d_in[5];
    const float* bv = (const float*)d_in[6];
    const float* Wo = (const float*)d_in[7];
    const float* bo = (const float*)d_in[8];
    const float* head_mask = (const float*)d_in[9];
    float* out = (float*)d_out;

    static bool attr_set = false;
    if (!attr_set) {
        cudaFuncSetAttribute(proj_tc, cudaFuncAttributeMaxDynamicSharedMemorySize, PROJ_SMEM);
        cudaFuncSetAttribute(attn_tc, cudaFuncAttributeMaxDynamicSharedMemorySize, ATTN_SMEM);
        attr_set = true;
    }

    // fp32 -> fp16 conversions
    const int xn4 = B_ * S_ * HID / 4;   // 2,097,152
    cvt_x<<<xn4 / 256, 256>>>((const float4*)x, xn4);
    cvt_w<<<(4 * HID * HID / 4) / 256, 256>>>((const float4*)Wq, (const float4*)Wk,
                                              (const float4*)Wv, (const float4*)Wo);

    __half* xh_dev;  cudaGetSymbolAddress((void**)&xh_dev,  g_xh);
    __half* ctx_dev; cudaGetSymbolAddress((void**)&ctx_dev, g_ctxh);

    // QKV projection: 12 x 64 blocks of 128m x 256n
    proj_tc<<<dim3(12, 64), 256, PROJ_SMEM>>>(xh_dev, 0, bq, bk, bv, bo, nullptr);

    // Attention: 16 q-tiles x 64 bh
    attn_tc<<<dim3(16, 64), 256, ATTN_SMEM>>>(head_mask);

    // O projection: 4 x 64
    proj_tc<<<dim3(4, 64), 256, PROJ_SMEM>>>(ctx_dev, 1, bq, bk, bv, bo, out);
}